// round 7
// baseline (speedup 1.0000x reference)
#include <cuda_runtime.h>
#include <cuda_bf16.h>

// dense_image_warp: out[b,y,x,c] = bilinear(image, (y,x) - flow[b,y,x,:])
// image: [B,H,W,C] f32, flow: [B,H,W,2] f32 (dy, dx). TFA clamping:
// floor clipped to [0, size-2], alpha clipped to [0,1].
//
// Block = 512 threads, tile = 128(x) x 8(y) pixels; each thread computes a
// VERTICAL pair of pixels (y, y+1). This doubles per-thread MLP (8 batched
// LDG.128) to saturate the L1 pipeline, and pixel A's bottom-row taps share
// L1 lines with pixel B's top-row taps.

static constexpr int B = 8;
static constexpr int H = 1024;
static constexpr int W = 768;
static constexpr int C = 3;
static constexpr int ROW_STRIDE = W * C;   // 2304 floats, %4==0 -> rows share alignment

static constexpr int TX = 128;             // tile x
static constexpr int TYP = 8;              // tile y (pixels)
static constexpr int THREADS = 512;        // each thread: 2 vertical pixels

__device__ __forceinline__ float sel4(float v0, float v1, float v2, float v3, int r) {
    return r == 0 ? v0 : (r == 1 ? v1 : (r == 2 ? v2 : v3));
}

__global__ __launch_bounds__(THREADS)
void warp_kernel(const float* __restrict__ image,
                 const float2* __restrict__ flow,
                 float4* __restrict__ out4)
{
    __shared__ float sbuf[TX * TYP * C];   // 3072 floats = 12 KB

    const int tid = threadIdx.x;
    const int xl  = tid & (TX - 1);        // 0..127
    const int ty  = tid >> 7;              // 0..3 -> pixel rows 2*ty, 2*ty+1

    const int x  = blockIdx.x * TX + xl;
    const int yA = blockIdx.y * TYP + ty * 2;
    const int b  = blockIdx.z;

    const int pixA = (b * H + yA) * W + x;
    const int pixB = pixA + W;

    float2 fA = flow[pixA];
    float2 fB = flow[pixB];

    // ---- address computation for both pixels ----
    int base[2], r[2];
    float ax[2], ay[2];
    {
        float qy = (float)yA - fA.x;
        float qx = (float)x  - fA.y;
        float y0f = fminf(fmaxf(floorf(qy), 0.0f), (float)(H - 2));
        float x0f = fminf(fmaxf(floorf(qx), 0.0f), (float)(W - 2));
        ay[0] = fminf(fmaxf(qy - y0f, 0.0f), 1.0f);
        ax[0] = fminf(fmaxf(qx - x0f, 0.0f), 1.0f);
        int pidx = ((b * H + (int)y0f) * W + (int)x0f) * C;
        base[0] = pidx & ~3;
        r[0]    = pidx & 3;
    }
    {
        float qy = (float)(yA + 1) - fB.x;
        float qx = (float)x        - fB.y;
        float y0f = fminf(fmaxf(floorf(qy), 0.0f), (float)(H - 2));
        float x0f = fminf(fmaxf(floorf(qx), 0.0f), (float)(W - 2));
        ay[1] = fminf(fmaxf(qy - y0f, 0.0f), 1.0f);
        ax[1] = fminf(fmaxf(qx - x0f, 0.0f), 1.0f);
        int pidx = ((b * H + (int)y0f) * W + (int)x0f) * C;
        base[1] = pidx & ~3;
        r[1]    = pidx & 3;
    }

    // ---- batch all 8 main loads for MLP ----
    float4 ta[2], tb[2], ba[2], bb[2];
    #pragma unroll
    for (int k = 0; k < 2; k++) {
        const float4* imgT = (const float4*)(image + base[k]);
        const float4* imgB = (const float4*)(image + base[k] + ROW_STRIDE);
        ta[k] = __ldg(imgT + 0);
        tb[k] = __ldg(imgT + 1);
        ba[k] = __ldg(imgB + 0);
        bb[k] = __ldg(imgB + 1);
    }
    float tc[2], bc[2];
    #pragma unroll
    for (int k = 0; k < 2; k++) {
        tc[k] = 0.0f; bc[k] = 0.0f;
        if (r[k] == 3) {
            tc[k] = __ldg(image + base[k] + 8);
            bc[k] = __ldg(image + base[k] + ROW_STRIDE + 8);
        }
    }

    // ---- compute + stage in smem ----
    #pragma unroll
    for (int k = 0; k < 2; k++) {
        int rr = r[k];
        float tl0 = sel4(ta[k].x, ta[k].y, ta[k].z, ta[k].w, rr);
        float tl1 = sel4(ta[k].y, ta[k].z, ta[k].w, tb[k].x, rr);
        float tl2 = sel4(ta[k].z, ta[k].w, tb[k].x, tb[k].y, rr);
        float tr0 = sel4(ta[k].w, tb[k].x, tb[k].y, tb[k].z, rr);
        float tr1 = sel4(tb[k].x, tb[k].y, tb[k].z, tb[k].w, rr);
        float tr2 = sel4(tb[k].y, tb[k].z, tb[k].w, tc[k],   rr);

        float bl0 = sel4(ba[k].x, ba[k].y, ba[k].z, ba[k].w, rr);
        float bl1 = sel4(ba[k].y, ba[k].z, ba[k].w, bb[k].x, rr);
        float bl2 = sel4(ba[k].z, ba[k].w, bb[k].x, bb[k].y, rr);
        float br0 = sel4(ba[k].w, bb[k].x, bb[k].y, bb[k].z, rr);
        float br1 = sel4(bb[k].x, bb[k].y, bb[k].z, bb[k].w, rr);
        float br2 = sel4(bb[k].y, bb[k].z, bb[k].w, bc[k],   rr);

        float axx = ax[k], ayy = ay[k];
        float top0 = tl0 + axx * (tr0 - tl0);
        float top1 = tl1 + axx * (tr1 - tl1);
        float top2 = tl2 + axx * (tr2 - tl2);
        float bot0 = bl0 + axx * (br0 - bl0);
        float bot1 = bl1 + axx * (br1 - bl1);
        float bot2 = bl2 + axx * (br2 - bl2);

        int sr = ty * 2 + k;               // sub-row 0..7
        float* s = sbuf + (sr * TX + xl) * 3;
        s[0] = top0 + ayy * (bot0 - top0);
        s[1] = top1 + ayy * (bot1 - top1);
        s[2] = top2 + ayy * (bot2 - top2);
    }

    __syncthreads();

    // ---- coalesced float4 stores: 8 rows * 96 float4 = 768 total ----
    const float4* s4 = (const float4*)sbuf;
    #pragma unroll
    for (int i = tid; i < TYP * 96; i += THREADS) {
        int sr = i / 96;                   // 0..7
        int j  = i - sr * 96;
        int yo = blockIdx.y * TYP + sr;
        int obase = (b * H + yo) * 576 + blockIdx.x * 96;
        out4[obase + j] = s4[i];
    }
}

extern "C" void kernel_launch(void* const* d_in, const int* in_sizes, int n_in,
                              void* d_out, int out_size)
{
    const float*  image = (const float*)d_in[0];
    const float2* flow  = (const float2*)d_in[1];
    float4*       out4  = (float4*)d_out;

    dim3 grid(W / TX, H / TYP, B);         // (6, 128, 8) exact
    warp_kernel<<<grid, THREADS>>>(image, flow, out4);
}

// round 8
// speedup vs baseline: 1.1023x; 1.1023x over previous
#include <cuda_runtime.h>
#include <cuda_bf16.h>

// dense_image_warp: out[b,y,x,c] = bilinear(image, (y,x) - flow[b,y,x,:])
// image: [B,H,W,C] f32, flow: [B,H,W,2] f32 (dy, dx). TFA clamping:
// floor clipped to [0, size-2], alpha clipped to [0,1].
//
// 256 threads, 1 pixel/thread, tile 128(x) x 2(y). Warp-autonomous epilogue:
// each warp stages its 32*3 outputs in a private smem strip and emits 24
// coalesced float4 stores after __syncwarp only (no block barrier).
// Bilinear evaluated vertical-first on raw vector lanes to minimize SEL count.

static constexpr int B = 8;
static constexpr int H = 1024;
static constexpr int W = 768;
static constexpr int C = 3;
static constexpr int ROW_STRIDE = W * C;   // 2304 floats, %4==0 -> rows share alignment

static constexpr int TX = 128;
static constexpr int TY = 2;
static constexpr int THREADS = 256;

__device__ __forceinline__ float sel4(float v0, float v1, float v2, float v3, int r) {
    return r == 0 ? v0 : (r == 1 ? v1 : (r == 2 ? v2 : v3));
}

__global__ __launch_bounds__(THREADS)
void warp_kernel(const float* __restrict__ image,
                 const float2* __restrict__ flow,
                 float4* __restrict__ out4)
{
    __shared__ float sbuf[8][96];          // per-warp staging, 3 KB

    const int tid  = threadIdx.x;
    const int wrp  = tid >> 5;             // 0..7
    const int lane = tid & 31;

    const int xl = tid & (TX - 1);         // 0..127
    const int ty = tid >> 7;               // 0..1  (== wrp>>2)

    const int x = blockIdx.x * TX + xl;
    const int y = blockIdx.y * TY + ty;
    const int b = blockIdx.z;

    const int pix = (b * H + y) * W + x;

    float2 f = flow[pix];                  // f.x = dy, f.y = dx
    float qy = (float)y - f.x;
    float qx = (float)x - f.y;

    float y0f = fminf(fmaxf(floorf(qy), 0.0f), (float)(H - 2));
    float x0f = fminf(fmaxf(floorf(qx), 0.0f), (float)(W - 2));
    float ay  = fminf(fmaxf(qy - y0f, 0.0f), 1.0f);
    float ax  = fminf(fmaxf(qx - x0f, 0.0f), 1.0f);

    int pidx = ((b * H + (int)y0f) * W + (int)x0f) * C;
    int base = pidx & ~3;                  // 16B-aligned float index
    int r    = pidx & 3;

    const float4* imgT = (const float4*)(image + base);
    const float4* imgB = (const float4*)(image + base + ROW_STRIDE);

    // Batch loads for MLP. Worst-case extra index (r==3) lands within image.
    float4 ta = __ldg(imgT + 0);
    float4 tb = __ldg(imgT + 1);
    float4 ba = __ldg(imgB + 0);
    float4 bb = __ldg(imgB + 1);
    float  t8 = 0.0f, b8 = 0.0f;
    if (r == 3) {
        t8 = __ldg(image + base + 8);
        b8 = __ldg(image + base + ROW_STRIDE + 8);
    }

    // Vertical lerp on the 9 raw lanes (FMA pipe).
    float v0 = ta.x + ay * (ba.x - ta.x);
    float v1 = ta.y + ay * (ba.y - ta.y);
    float v2 = ta.z + ay * (ba.z - ta.z);
    float v3 = ta.w + ay * (ba.w - ta.w);
    float v4 = tb.x + ay * (bb.x - tb.x);
    float v5 = tb.y + ay * (bb.y - tb.y);
    float v6 = tb.z + ay * (bb.z - tb.z);
    float v7 = tb.w + ay * (bb.w - tb.w);
    float v8 = t8   + ay * (b8   - t8);

    // Horizontal lerp: u[j] pairs lane j with lane j+3.
    float u0 = v0 + ax * (v3 - v0);
    float u1 = v1 + ax * (v4 - v1);
    float u2 = v2 + ax * (v5 - v2);
    float u3 = v3 + ax * (v6 - v3);
    float u4 = v4 + ax * (v7 - v4);
    float u5 = v5 + ax * (v8 - v5);

    // Extract the 3 output channels (lanes r, r+1, r+2 of u).
    float o0 = sel4(u0, u1, u2, u3, r);
    float o1 = sel4(u1, u2, u3, u4, r);
    float o2 = sel4(u2, u3, u4, u5, r);

    // Warp-local staging + coalesced store (no block barrier).
    float* s = &sbuf[wrp][lane * 3];
    s[0] = o0;
    s[1] = o1;
    s[2] = o2;
    __syncwarp();

    if (lane < 24) {
        const float4* s4 = (const float4*)sbuf[wrp];
        int seg = wrp & 3;                 // x-segment of 32 px within the 128-px row
        int obase = (b * H + y) * 576 + blockIdx.x * 96 + seg * 24;
        out4[obase + lane] = s4[lane];
    }
}

extern "C" void kernel_launch(void* const* d_in, const int* in_sizes, int n_in,
                              void* d_out, int out_size)
{
    const float*  image = (const float*)d_in[0];
    const float2* flow  = (const float2*)d_in[1];
    float4*       out4  = (float4*)d_out;

    dim3 grid(W / TX, H / TY, B);          // (6, 512, 8) exact
    warp_kernel<<<grid, THREADS>>>(image, flow, out4);
}

// round 10
// speedup vs baseline: 1.1739x; 1.0649x over previous
#include <cuda_runtime.h>
#include <cuda_bf16.h>
#include <cstdint>

// dense_image_warp: out[b,y,x,c] = bilinear(image, (y,x) - flow[b,y,x,:])
// image: [B,H,W,C] f32, flow: [B,H,W,2] f32 (dy, dx). TFA clamping:
// floor clipped to [0, size-2], alpha clipped to [0,1].
//
// 256 threads, 1 pixel/thread, tile 128(x) x 2(y). Vertical-first bilinear on
// raw vector lanes (minimal SELs). Epilogue: results staged in smem (STS only),
// then drained to global via cp.async.bulk (TMA path) -- no LDS/STG through L1.

static constexpr int B = 8;
static constexpr int H = 1024;
static constexpr int W = 768;
static constexpr int C = 3;
static constexpr int ROW_STRIDE = W * C;   // 2304 floats, %4==0 -> rows share alignment

static constexpr int TX = 128;
static constexpr int TY = 2;
static constexpr int THREADS = 256;
static constexpr int ROW_SEG_FLOATS = TX * C;         // 384 floats = 1536 B per tile row

__device__ __forceinline__ float sel4(float v0, float v1, float v2, float v3, int r) {
    return r == 0 ? v0 : (r == 1 ? v1 : (r == 2 ? v2 : v3));
}

__global__ __launch_bounds__(THREADS)
void warp_kernel(const float* __restrict__ image,
                 const float2* __restrict__ flow,
                 float* __restrict__ out)
{
    __shared__ alignas(16) float sbuf[TY][ROW_SEG_FLOATS];   // 3 KB

    const int tid = threadIdx.x;
    const int xl  = tid & (TX - 1);        // 0..127
    const int ty  = tid >> 7;              // 0..1

    const int x = blockIdx.x * TX + xl;
    const int y = blockIdx.y * TY + ty;
    const int b = blockIdx.z;

    const int pix = (b * H + y) * W + x;

    float2 f = flow[pix];                  // f.x = dy, f.y = dx
    float qy = (float)y - f.x;
    float qx = (float)x - f.y;

    float y0f = fminf(fmaxf(floorf(qy), 0.0f), (float)(H - 2));
    float x0f = fminf(fmaxf(floorf(qx), 0.0f), (float)(W - 2));
    float ay  = fminf(fmaxf(qy - y0f, 0.0f), 1.0f);
    float ax  = fminf(fmaxf(qx - x0f, 0.0f), 1.0f);

    int pidx = ((b * H + (int)y0f) * W + (int)x0f) * C;
    int base = pidx & ~3;                  // 16B-aligned float index
    int r    = pidx & 3;

    const float4* imgT = (const float4*)(image + base);
    const float4* imgB = (const float4*)(image + base + ROW_STRIDE);

    // Batch loads for MLP. Worst-case extra index (r==3) lands within image.
    float4 ta = __ldg(imgT + 0);
    float4 tb = __ldg(imgT + 1);
    float4 ba = __ldg(imgB + 0);
    float4 bb = __ldg(imgB + 1);
    float  t8 = 0.0f, b8 = 0.0f;
    if (r == 3) {
        t8 = __ldg(image + base + 8);
        b8 = __ldg(image + base + ROW_STRIDE + 8);
    }

    // Vertical lerp on the 9 raw lanes (FMA pipe).
    float v0 = ta.x + ay * (ba.x - ta.x);
    float v1 = ta.y + ay * (ba.y - ta.y);
    float v2 = ta.z + ay * (ba.z - ta.z);
    float v3 = ta.w + ay * (ba.w - ta.w);
    float v4 = tb.x + ay * (bb.x - tb.x);
    float v5 = tb.y + ay * (bb.y - tb.y);
    float v6 = tb.z + ay * (bb.z - tb.z);
    float v7 = tb.w + ay * (bb.w - tb.w);
    float v8 = t8   + ay * (b8   - t8);

    // Horizontal lerp: u[j] pairs lane j with lane j+3.
    float u0 = v0 + ax * (v3 - v0);
    float u1 = v1 + ax * (v4 - v1);
    float u2 = v2 + ax * (v5 - v2);
    float u3 = v3 + ax * (v6 - v3);
    float u4 = v4 + ax * (v7 - v4);
    float u5 = v5 + ax * (v8 - v5);

    // Extract the 3 output channels (lanes r, r+1, r+2 of u).
    float* s = &sbuf[ty][xl * 3];
    s[0] = sel4(u0, u1, u2, u3, r);
    s[1] = sel4(u1, u2, u3, u4, r);
    s[2] = sel4(u2, u3, u4, u5, r);

    __syncthreads();

    // Drain smem -> global via the bulk-async (TMA) path: no L1 LDS/STG.
    if (tid == 0) {
        asm volatile("fence.proxy.async.shared::cta;" ::: "memory");
        uint32_t s0;
        asm("{ .reg .u64 t; cvta.to.shared.u64 t, %1; cvt.u32.u64 %0, t; }"
            : "=r"(s0) : "l"(&sbuf[0][0]));

        #pragma unroll
        for (int rr = 0; rr < TY; rr++) {
            int yo = blockIdx.y * TY + rr;
            float* gdst = out + ((size_t)(b * H + yo) * W + blockIdx.x * TX) * C;
            asm volatile(
                "cp.async.bulk.global.shared::cta.bulk_group [%0], [%1], %2;"
                :: "l"(gdst), "r"(s0 + rr * (ROW_SEG_FLOATS * 4)),
                   "n"(ROW_SEG_FLOATS * 4)
                : "memory");
        }
        asm volatile("cp.async.bulk.commit_group;" ::: "memory");
        asm volatile("cp.async.bulk.wait_group 0;" ::: "memory");
    }
}

extern "C" void kernel_launch(void* const* d_in, const int* in_sizes, int n_in,
                              void* d_out, int out_size)
{
    const float*  image = (const float*)d_in[0];
    const float2* flow  = (const float2*)d_in[1];
    float*        outp  = (float*)d_out;

    dim3 grid(W / TX, H / TY, B);          // (6, 512, 8) exact
    warp_kernel<<<grid, THREADS>>>(image, flow, outp);
}